// round 14
// baseline (speedup 1.0000x reference)
#include <cuda_runtime.h>
#include <cuda_fp16.h>
#include <cstdint>

// ---------------------------------------------------------------------------
// PriorNetwork round 14: fp16 mma.sync scoring with cp.async triple-buffered
// staging (no register staging), ks-outer MMA ordering (dep distance 16),
// in-place half2 epilogue + branch-skip rescue (EPS=4.0 hard bound);
// exact fp32 rescore; fused MLP QB=4 with stage-2 chain splitting.
// ---------------------------------------------------------------------------

#define D     64
#define H     512
#define QT    128
#define NT    128
#define CAP   4096
#define EPS   4.0f
#define NPAD  100480
#define BQ    2048
#define QB    4

#define BSTRIDE 40                       // words per tile row (16B-aligned)
#define BWORDS  (NT * BSTRIDE)           // 5120 words per buffer
#define NBUF    3
#define SM_WORDS (128 + NBUF * 64 + NBUF * BWORDS)   // 15680 words = 62720 B

__device__ unsigned long long g_best[BQ];
__device__ float    g_t2[NPAD];
__device__ uint32_t g_t2h[NPAD / 2];          // half2 packed t2 (col pairs)
__device__ uint32_t g_trh[(size_t)NPAD * 32]; // f16 train, pre-swizzled words
__device__ int      g_ccnt[BQ];
__device__ int      g_cand[BQ * CAP];

// ---- helpers --------------------------------------------------------------

__device__ __forceinline__ unsigned enc_f32(float f) {
    unsigned u = __float_as_uint(f);
    return (u & 0x80000000u) ? ~u : (u | 0x80000000u);
}
__device__ __forceinline__ float dec_f32(unsigned e) {
    unsigned u = (e & 0x80000000u) ? (e ^ 0x80000000u) : ~e;
    return __uint_as_float(u);
}
__device__ __forceinline__ uint32_t hfp(float lo, float hi) {   // {lo,hi} f16x2
    uint32_t r;
    asm("cvt.rn.f16x2.f32 %0, %1, %2;" : "=r"(r) : "f"(hi), "f"(lo));
    return r;
}
__device__ __forceinline__ void mma_f16(uint32_t& c0, uint32_t& c1,
                                        const uint32_t* a,
                                        uint32_t b0, uint32_t b1) {
    asm("mma.sync.aligned.m16n8k16.row.col.f16.f16.f16.f16 "
        "{%0,%1}, {%2,%3,%4,%5}, {%6,%7}, {%0,%1};"
        : "+r"(c0), "+r"(c1)
        : "r"(a[0]), "r"(a[1]), "r"(a[2]), "r"(a[3]), "r"(b0), "r"(b1));
}
__device__ __forceinline__ void cp16(uint32_t dst, const void* src) {
    asm volatile("cp.async.cg.shared.global [%0], [%1], 16;"
                 :: "r"(dst), "l"(src));
}
#define CP_COMMIT() asm volatile("cp.async.commit_group;")
#define CP_WAIT1()  asm volatile("cp.async.wait_group 1;")

// ---- k_prep: t2, t2h, pre-swizzled f16 train (chunked x3) -----------------
// word w at row n holds train[n][k0..k0+1], where wx = w ^ ((n&1)<<1),
//   ks = wx>>3, hh = wx&1, r4a = (wx&7)>>1, k0 = ks*16 + hh*8 + 2*r4a.

__global__ void k_prep(const float* __restrict__ train, int N, int B,
                       int base, int cnt) {
    int i = blockIdx.x * blockDim.x + threadIdx.x;
    if (base == 0 && i < B) g_ccnt[i] = 0;
    int n = base + i;
    if (i >= cnt || n >= NPAD) return;

    if (n < N) {
        const float* row = train + (size_t)n * D;
        float s = 0.f;
        for (int k = 0; k < D; k += 4) {
            float4 v = *(const float4*)&row[k];
            s += v.x * v.x + v.y * v.y + v.z * v.z + v.w * v.w;
        }
        g_t2[n] = s;
        ((__half*)g_t2h)[n] = __float2half_rn(s);
        const int px = (n & 1) << 1;
#pragma unroll
        for (int w = 0; w < 32; w++) {
            int wx  = w ^ px;
            int ks  = wx >> 3;
            int hh  = wx & 1;
            int r4a = (wx & 7) >> 1;
            int k0  = ks * 16 + hh * 8 + 2 * r4a;
            float2 p = *(const float2*)&row[k0];
            g_trh[(size_t)n * 32 + w] = hfp(p.x, p.y);
        }
    } else {
        g_t2[n] = 3.0e38f;
        ((__half*)g_t2h)[n] = __float2half_rn(3.0e38f);   // -> +inf
#pragma unroll
        for (int w = 0; w < 32; w++) g_trh[(size_t)n * 32 + w] = 0u;
    }
}

// ---- k_score --------------------------------------------------------------

// Stage tile t into smem buffer via cp.async (4x16B rows + t2 strip).
__device__ __forceinline__ void stage_tile(uint32_t bdst, uint32_t t2dst,
                                           int t, int tid) {
    const int n  = tid >> 1;
    const int hf = tid & 1;
    const char* src = (const char*)(g_trh + (size_t)(t * NT + n) * 32 + hf * 16);
    uint32_t dst = bdst + (uint32_t)(n * BSTRIDE + hf * 16) * 4u;
#pragma unroll
    for (int i = 0; i < 4; i++) cp16(dst + i * 16, src + i * 16);
    if (tid < 16)
        cp16(t2dst + tid * 16, (const char*)(g_t2h + t * 64 + tid * 4));
}

__global__ void __launch_bounds__(256, 2)
k_score(const float* __restrict__ codes, int tiles_total, int tps) {
    extern __shared__ uint32_t smw[];
    unsigned* cmin  = (unsigned*)smw;                 // [128]
    uint32_t* t2hb  = smw + 128;                      // [NBUF][64]
    uint32_t* Bw    = smw + 128 + NBUF * 64;          // [NBUF][BWORDS]

    const uint32_t sb      = (uint32_t)__cvta_generic_to_shared(smw);
    const uint32_t t2base  = sb + 128u * 4u;
    const uint32_t bbase   = sb + (128u + NBUF * 64u) * 4u;

    const int tid  = threadIdx.x;
    const int lane = tid & 31;
    const int wid  = tid >> 5;
    const int wm   = wid >> 1;
    const int wn   = wid & 1;
    const int g    = lane >> 2;
    const int r4   = lane & 3;
    const int px   = (g & 1) << 1;
    const int qbase = blockIdx.x * QT;

    const int t0 = blockIdx.y * tps;
    const int t1 = min(t0 + tps, tiles_total);
    if (t0 >= t1) return;

    if (tid < QT) cmin[tid] = enc_f32(3.0e38f);

    // Prologue: async-stage tiles t0 and t0+1 (one commit group each).
    stage_tile(bbase, t2base, t0, tid);
    CP_COMMIT();
    if (t0 + 1 < t1)
        stage_tile(bbase + BWORDS * 4u, t2base + 64u * 4u, t0 + 1, tid);
    CP_COMMIT();

    // A fragments (f16): afr[mi][ks][4]  (loads overlap the cp.asyncs)
    uint32_t afr[2][4][4];
#pragma unroll
    for (int mi = 0; mi < 2; mi++) {
        const int qr = qbase + wm * 32 + mi * 16 + g;
#pragma unroll
        for (int ks = 0; ks < 4; ks++) {
            const int k0 = ks * 16 + 2 * r4;
            float2 p0 = __ldg((const float2*)&codes[(size_t)qr * D + k0]);
            float2 p1 = __ldg((const float2*)&codes[(size_t)(qr + 8) * D + k0]);
            float2 p2 = __ldg((const float2*)&codes[(size_t)qr * D + k0 + 8]);
            float2 p3 = __ldg((const float2*)&codes[(size_t)(qr + 8) * D + k0 + 8]);
            afr[mi][ks][0] = hfp(p0.x, p0.y);
            afr[mi][ks][1] = hfp(p1.x, p1.y);
            afr[mi][ks][2] = hfp(p2.x, p2.y);
            afr[mi][ks][3] = hfp(p3.x, p3.y);
        }
    }

    // slot = mi*2 + reg (reg 0: row g, reg 1: row g+8)
    int qloc[4];
#pragma unroll
    for (int s = 0; s < 4; s++)
        qloc[s] = wm * 32 + (s >> 1) * 16 + g + (s & 1) * 8;

    CP_WAIT1();          // tile t0 resident (t0+1 may be in flight)
    __syncthreads();

    const __half2 neg2 = __floats2half2_rn(-2.f, -2.f);

    for (int t = t0; t < t1; t++) {
        const int p = (t - t0) % 3;
        const uint32_t* Bc  = Bw + p * BWORDS;
        const uint32_t* t2c = t2hb + p * 64;

        uint32_t acc[2][8][2];
#pragma unroll
        for (int mi = 0; mi < 2; mi++)
#pragma unroll
            for (int j = 0; j < 8; j++) { acc[mi][j][0] = 0u; acc[mi][j][1] = 0u; }

        // ks-outer: 16 independent MMAs between dependent ones.
#pragma unroll
        for (int ks = 0; ks < 4; ks++) {
            uint2 b[8];
#pragma unroll
            for (int j = 0; j < 8; j++)
                b[j] = *(const uint2*)(Bc + (wn * 64 + j * 8 + g) * BSTRIDE +
                                       ((2 * r4) ^ px) + ks * 8);
#pragma unroll
            for (int j = 0; j < 8; j++) {
                mma_f16(acc[0][j][0], acc[0][j][1], afr[0][ks], b[j].x, b[j].y);
                mma_f16(acc[1][j][0], acc[1][j][1], afr[1][ks], b[j].x, b[j].y);
            }
        }

        // Stage tile t+2 into the buffer tile t-1 vacated last iteration.
        if (t + 2 < t1) {
            const int p2 = (p + 2) % 3;
            stage_tile(bbase + (uint32_t)p2 * BWORDS * 4u,
                       t2base + (uint32_t)p2 * 64u * 4u, t + 2, tid);
        }
        CP_COMMIT();     // unconditional: keeps wait_group numbering uniform

        // Epilogue IN PLACE: acc <- t2 - 2*acc (half2 scores).
#pragma unroll
        for (int j = 0; j < 8; j++) {
            __half2 t2p = *(const __half2*)&t2c[wn * 32 + j * 4 + r4];
#pragma unroll
            for (int mi = 0; mi < 2; mi++) {
                *(__half2*)&acc[mi][j][0] =
                    __hfma2(*(__half2*)&acc[mi][j][0], neg2, t2p);
                *(__half2*)&acc[mi][j][1] =
                    __hfma2(*(__half2*)&acc[mi][j][1], neg2, t2p);
            }
        }

        // Per-slot tile minima + thresholds (own-tile min folded in: safe).
        float mf[4], thr[4];
        bool trigger = false;
#pragma unroll
        for (int s = 0; s < 4; s++) {
            const int mi = s >> 1, r = s & 1;
            __half2 m = *(__half2*)&acc[mi][0][r];
#pragma unroll
            for (int j = 1; j < 8; j++) m = __hmin2(m, *(__half2*)&acc[mi][j][r]);
            mf[s]  = __half2float(__hmin(__low2half(m), __high2half(m)));
            thr[s] = fminf(dec_f32(cmin[qloc[s]]), mf[s]) + EPS;
            trigger |= (mf[s] <= thr[s]);
        }

        if (trigger) {
            const int n0 = t * NT + wn * 64 + 2 * r4;
#pragma unroll
            for (int s = 0; s < 4; s++) {
                const int mi = s >> 1, r = s & 1;
                if (mf[s] > thr[s]) continue;
                const int q = qbase + qloc[s];
#pragma unroll
                for (int j = 0; j < 8; j++) {
                    __half2 sp = *(__half2*)&acc[mi][j][r];
                    float slo = __half2float(__low2half(sp));
                    float shi = __half2float(__high2half(sp));
                    if (slo <= thr[s]) {
                        int pos = atomicAdd(&g_ccnt[q], 1);
                        if (pos < CAP) g_cand[q * CAP + pos] = n0 + j * 8;
                    }
                    if (shi <= thr[s]) {
                        int pos = atomicAdd(&g_ccnt[q], 1);
                        if (pos < CAP) g_cand[q * CAP + pos] = n0 + j * 8 + 1;
                    }
                }
            }
        }

        // Unconditional publish of tile minima to shared running min.
        float tm[4] = {mf[0], mf[1], mf[2], mf[3]};
#pragma unroll
        for (int s = 0; s < 4; s++) {
            tm[s] = fminf(tm[s], __shfl_xor_sync(0xffffffffu, tm[s], 1));
            tm[s] = fminf(tm[s], __shfl_xor_sync(0xffffffffu, tm[s], 2));
        }
        if (r4 == 0) {
#pragma unroll
            for (int s = 0; s < 4; s++)
                atomicMin(&cmin[qloc[s]], enc_f32(tm[s]));
        }

        CP_WAIT1();      // tile t+1 resident (t+2 may be in flight)
        __syncthreads();
    }
}

// ---- exact fp32 rescore (one warp per query) ------------------------------

__global__ void __launch_bounds__(256)
k_rescore(const float* __restrict__ codes, const float* __restrict__ train,
          int B) {
    const int lane = threadIdx.x & 31;
    const int q = blockIdx.x * 8 + (threadIdx.x >> 5);
    if (q >= B) return;

    float4 qv[16];
#pragma unroll
    for (int i = 0; i < 16; i++)
        qv[i] = __ldg(&((const float4*)codes)[(size_t)q * 16 + i]);

    unsigned long long best = 0xFFFFFFFFFFFFFFFFULL;
    int cnt = min(g_ccnt[q], CAP);
    for (int i = lane; i < cnt; i += 32) {
        int n = g_cand[q * CAP + i];
        const float4* tr = (const float4*)(train + (size_t)n * D);
        float dot = 0.f;
#pragma unroll
        for (int k = 0; k < 16; k++) {
            float4 tv = __ldg(&tr[k]);
            dot = fmaf(qv[k].x, tv.x, dot);
            dot = fmaf(qv[k].y, tv.y, dot);
            dot = fmaf(qv[k].z, tv.z, dot);
            dot = fmaf(qv[k].w, tv.w, dot);
        }
        float s = fmaf(-2.f, dot, g_t2[n]);
        unsigned long long key =
            ((unsigned long long)enc_f32(s) << 32) | (unsigned)n;
        best = min(best, key);
    }
#pragma unroll
    for (int off = 16; off >= 1; off >>= 1)
        best = min(best, __shfl_xor_sync(0xffffffffu, best, off));
    if (lane == 0) g_best[q] = best;
}

// ---- fused MLP: 4 queries per CTA, stage-2 chain splitting ----------------

__global__ void __launch_bounds__(256)
k_mlp(const float* __restrict__ train,
      const float* __restrict__ W1, const float* __restrict__ b1,
      const float* __restrict__ Wu, const float* __restrict__ bu,
      const float* __restrict__ Ws, const float* __restrict__ bs,
      float* __restrict__ out, int B, int N) {
    __shared__ float x_s[QB][D];
    __shared__ float h_s[QB][H];
    const int qb  = blockIdx.x * QB;
    const int tid = threadIdx.x;

    if (tid < QB * (D / 4)) {
        int q  = tid >> 4;
        int c4 = tid & 15;
        unsigned ch = (unsigned)(g_best[qb + q] & 0xFFFFFFFFULL);
        ch = min(ch, (unsigned)(N - 1));    // crash guard; logic keeps it < N
        ((float4*)&x_s[q][0])[c4] =
            __ldg(&((const float4*)train)[(size_t)ch * (D / 4) + c4]);
    }
    __syncthreads();

    {   // h = relu(x @ W1 + b1): thread owns columns tid, tid+256
        float a0[QB], a1[QB];
#pragma unroll
        for (int q = 0; q < QB; q++) { a0[q] = 0.f; a1[q] = 0.f; }
        const int c0 = tid, c1 = tid + 256;
#pragma unroll 4
        for (int d = 0; d < D; d++) {
            float w0 = __ldg(&W1[d * H + c0]);
            float w1 = __ldg(&W1[d * H + c1]);
#pragma unroll
            for (int q = 0; q < QB; q++) {
                float x = x_s[q][d];
                a0[q] = fmaf(x, w0, a0[q]);
                a1[q] = fmaf(x, w1, a1[q]);
            }
        }
        float bb0 = __ldg(&b1[c0]), bb1 = __ldg(&b1[c1]);
#pragma unroll
        for (int q = 0; q < QB; q++) {
            h_s[q][c0] = fmaxf(a0[q] + bb0, 0.f);
            h_s[q][c1] = fmaxf(a1[q] + bb1, 0.f);
        }
    }
    __syncthreads();

    {   // mu / logstd: thread -> (d, which, 2-query half); 4-way chain split
        const int d     = tid & 63;
        const int which = (tid >> 6) & 1;
        const int qh    = tid >> 7;
        const float* W  = which ? Ws : Wu;
        const float* bb = which ? bs : bu;
        float a0[4] = {0.f, 0.f, 0.f, 0.f};
        float a1[4] = {0.f, 0.f, 0.f, 0.f};
        const float* h0 = h_s[qh * 2];
        const float* h1 = h_s[qh * 2 + 1];
#pragma unroll 2
        for (int h = 0; h < H; h += 4) {
#pragma unroll
            for (int u = 0; u < 4; u++) {
                float w = __ldg(&W[(size_t)(h + u) * D + d]);
                a0[u] = fmaf(h0[h + u], w, a0[u]);
                a1[u] = fmaf(h1[h + u], w, a1[u]);
            }
        }
        float bvv = __ldg(&bb[d]);
        float r0 = (a0[0] + a0[1]) + (a0[2] + a0[3]) + bvv;
        float r1 = (a1[0] + a1[1]) + (a1[2] + a1[3]) + bvv;
        out[(size_t)which * B * D + (size_t)(qb + qh * 2) * D + d]     = r0;
        out[(size_t)which * B * D + (size_t)(qb + qh * 2 + 1) * D + d] = r1;
    }
}

// ---- launch ---------------------------------------------------------------

extern "C" void kernel_launch(void* const* d_in, const int* in_sizes, int n_in,
                              void* d_out, int out_size) {
    const float* codes = (const float*)d_in[0];
    const float* train = (const float*)d_in[1];
    const float* W1    = (const float*)d_in[2];
    const float* b1    = (const float*)d_in[3];
    const float* Wu    = (const float*)d_in[4];
    const float* bu    = (const float*)d_in[5];
    const float* Ws    = (const float*)d_in[6];
    const float* bs    = (const float*)d_in[7];
    float* out = (float*)d_out;

    const int B = in_sizes[0] / D;   // 2048
    const int N = in_sizes[1] / D;   // 100000

    // 3 prep chunks (keeps k_score at the ncu capture slot).
    const int CH = 33536;            // 131 * 256
    k_prep<<<131, 256>>>(train, N, B, 0, CH);
    k_prep<<<131, 256>>>(train, N, B, CH, CH);
    k_prep<<<131, 256>>>(train, N, B, 2 * CH, NPAD - 2 * CH);

    const int tiles_total = (N + NT - 1) / NT;          // 782
    const int qtiles      = B / QT;                     // 16
    const int nsplits     = 18;                         // 288 CTAs = 2/SM wave
    const int tps         = (tiles_total + nsplits - 1) / nsplits;

    const size_t smem = (size_t)SM_WORDS * sizeof(uint32_t);   // 62720 B
    cudaFuncSetAttribute(k_score, cudaFuncAttributeMaxDynamicSharedMemorySize,
                         (int)smem);
    k_score<<<dim3(qtiles, nsplits), 256, smem>>>(codes, tiles_total, tps);

    k_rescore<<<(B + 7) / 8, 256>>>(codes, train, B);
    k_mlp<<<B / QB, 256>>>(train, W1, b1, Wu, bu, Ws, bs, out, B, N);
}

// round 15
// speedup vs baseline: 1.2218x; 1.2218x over previous
#include <cuda_runtime.h>
#include <cuda_fp16.h>
#include <cstdint>

// ---------------------------------------------------------------------------
// PriorNetwork round 15: 512-thread k_score (16 warps, m16 per warp) for
// 32 warps/SM; fp16 mma.sync, cp.async NBUF=3 staging, in-place half2
// epilogue + branch-skip rescue (EPS=4.0 hard bound); exact fp32 rescore;
// fused MLP QB=4.
// ---------------------------------------------------------------------------

#define D     64
#define H     512
#define QT    128
#define NT    128
#define CAP   4096
#define EPS   4.0f
#define NPAD  100480
#define BQ    2048
#define QB    4

#define BSTRIDE 40                       // words per tile row (16B-aligned)
#define BWORDS  (NT * BSTRIDE)           // 5120 words per buffer
#define NBUF    3
#define SM_WORDS (128 + NBUF * 64 + NBUF * BWORDS)   // 15680 words = 62720 B

__device__ unsigned long long g_best[BQ];
__device__ float    g_t2[NPAD];
__device__ uint32_t g_t2h[NPAD / 2];          // half2 packed t2 (col pairs)
__device__ uint32_t g_trh[(size_t)NPAD * 32]; // f16 train, pre-swizzled words
__device__ int      g_ccnt[BQ];
__device__ int      g_cand[BQ * CAP];

// ---- helpers --------------------------------------------------------------

__device__ __forceinline__ unsigned enc_f32(float f) {
    unsigned u = __float_as_uint(f);
    return (u & 0x80000000u) ? ~u : (u | 0x80000000u);
}
__device__ __forceinline__ float dec_f32(unsigned e) {
    unsigned u = (e & 0x80000000u) ? (e ^ 0x80000000u) : ~e;
    return __uint_as_float(u);
}
__device__ __forceinline__ uint32_t hfp(float lo, float hi) {   // {lo,hi} f16x2
    uint32_t r;
    asm("cvt.rn.f16x2.f32 %0, %1, %2;" : "=r"(r) : "f"(hi), "f"(lo));
    return r;
}
__device__ __forceinline__ void mma_f16(uint32_t& c0, uint32_t& c1,
                                        const uint32_t* a,
                                        uint32_t b0, uint32_t b1) {
    asm("mma.sync.aligned.m16n8k16.row.col.f16.f16.f16.f16 "
        "{%0,%1}, {%2,%3,%4,%5}, {%6,%7}, {%0,%1};"
        : "+r"(c0), "+r"(c1)
        : "r"(a[0]), "r"(a[1]), "r"(a[2]), "r"(a[3]), "r"(b0), "r"(b1));
}
__device__ __forceinline__ void cp16(uint32_t dst, const void* src) {
    asm volatile("cp.async.cg.shared.global [%0], [%1], 16;"
                 :: "r"(dst), "l"(src));
}
#define CP_COMMIT() asm volatile("cp.async.commit_group;")
#define CP_WAIT1()  asm volatile("cp.async.wait_group 1;")

// ---- k_prep: t2, t2h, pre-swizzled f16 train (chunked x3) -----------------
// word w at row n holds train[n][k0..k0+1], where wx = w ^ ((n&1)<<1),
//   ks = wx>>3, hh = wx&1, r4a = (wx&7)>>1, k0 = ks*16 + hh*8 + 2*r4a.

__global__ void k_prep(const float* __restrict__ train, int N, int B,
                       int base, int cnt) {
    int i = blockIdx.x * blockDim.x + threadIdx.x;
    if (base == 0 && i < B) g_ccnt[i] = 0;
    int n = base + i;
    if (i >= cnt || n >= NPAD) return;

    if (n < N) {
        const float* row = train + (size_t)n * D;
        float s = 0.f;
        for (int k = 0; k < D; k += 4) {
            float4 v = *(const float4*)&row[k];
            s += v.x * v.x + v.y * v.y + v.z * v.z + v.w * v.w;
        }
        g_t2[n] = s;
        ((__half*)g_t2h)[n] = __float2half_rn(s);
        const int px = (n & 1) << 1;
#pragma unroll
        for (int w = 0; w < 32; w++) {
            int wx  = w ^ px;
            int ks  = wx >> 3;
            int hh  = wx & 1;
            int r4a = (wx & 7) >> 1;
            int k0  = ks * 16 + hh * 8 + 2 * r4a;
            float2 p = *(const float2*)&row[k0];
            g_trh[(size_t)n * 32 + w] = hfp(p.x, p.y);
        }
    } else {
        g_t2[n] = 3.0e38f;
        ((__half*)g_t2h)[n] = __float2half_rn(3.0e38f);   // -> +inf
#pragma unroll
        for (int w = 0; w < 32; w++) g_trh[(size_t)n * 32 + w] = 0u;
    }
}

// ---- k_score (512 threads, 16 warps, m16 per warp) ------------------------

// Stage tile t into smem buffer via cp.async: 1024 16B chunks + t2 strip.
__device__ __forceinline__ void stage_tile(uint32_t bdst, uint32_t t2dst,
                                           int t, int tid) {
#pragma unroll
    for (int u = 0; u < 2; u++) {
        int c   = tid + u * 512;          // chunk 0..1023
        int n   = c >> 3;                 // row 0..127
        int off = (c & 7) * 4;            // word offset 0..28
        const char* src = (const char*)(g_trh + (size_t)(t * NT + n) * 32 + off);
        cp16(bdst + (uint32_t)(n * BSTRIDE + off) * 4u, src);
    }
    if (tid < 16)
        cp16(t2dst + tid * 16, (const char*)(g_t2h + t * 64 + tid * 4));
}

__global__ void __launch_bounds__(512, 2)
k_score(const float* __restrict__ codes, int tiles_total, int tps) {
    extern __shared__ uint32_t smw[];
    unsigned* cmin  = (unsigned*)smw;                 // [128]
    uint32_t* t2hb  = smw + 128;                      // [NBUF][64]
    uint32_t* Bw    = smw + 128 + NBUF * 64;          // [NBUF][BWORDS]

    const uint32_t sb      = (uint32_t)__cvta_generic_to_shared(smw);
    const uint32_t t2base  = sb + 128u * 4u;
    const uint32_t bbase   = sb + (128u + NBUF * 64u) * 4u;

    const int tid  = threadIdx.x;
    const int lane = tid & 31;
    const int wid  = tid >> 5;        // 0..15
    const int wm   = wid >> 1;        // 0..7 : m16 strip
    const int wn   = wid & 1;         // 0..1 : n64 strip
    const int g    = lane >> 2;       // 0..7
    const int r4   = lane & 3;        // 0..3
    const int px   = (g & 1) << 1;
    const int qbase = blockIdx.x * QT;

    const int t0 = blockIdx.y * tps;
    const int t1 = min(t0 + tps, tiles_total);
    if (t0 >= t1) return;

    if (tid < QT) cmin[tid] = enc_f32(3.0e38f);

    // Prologue: async-stage tiles t0 and t0+1 (one commit group each).
    stage_tile(bbase, t2base, t0, tid);
    CP_COMMIT();
    if (t0 + 1 < t1)
        stage_tile(bbase + BWORDS * 4u, t2base + 64u * 4u, t0 + 1, tid);
    CP_COMMIT();

    // A fragments (f16), m16 strip: afr[ks][4]
    uint32_t afr[4][4];
    {
        const int qr = qbase + wm * 16 + g;
#pragma unroll
        for (int ks = 0; ks < 4; ks++) {
            const int k0 = ks * 16 + 2 * r4;
            float2 p0 = __ldg((const float2*)&codes[(size_t)qr * D + k0]);
            float2 p1 = __ldg((const float2*)&codes[(size_t)(qr + 8) * D + k0]);
            float2 p2 = __ldg((const float2*)&codes[(size_t)qr * D + k0 + 8]);
            float2 p3 = __ldg((const float2*)&codes[(size_t)(qr + 8) * D + k0 + 8]);
            afr[ks][0] = hfp(p0.x, p0.y);
            afr[ks][1] = hfp(p1.x, p1.y);
            afr[ks][2] = hfp(p2.x, p2.y);
            afr[ks][3] = hfp(p3.x, p3.y);
        }
    }

    // slot 0: row g, slot 1: row g+8 (within m16 strip)
    const int qloc0 = wm * 16 + g;
    const int qloc1 = wm * 16 + g + 8;

    CP_WAIT1();          // tile t0 resident (t0+1 may be in flight)
    __syncthreads();

    const __half2 neg2 = __floats2half2_rn(-2.f, -2.f);

    for (int t = t0; t < t1; t++) {
        const int p = (t - t0) % 3;
        const uint32_t* Bc  = Bw + p * BWORDS;
        const uint32_t* t2c = t2hb + p * 64;

        uint32_t acc[8][2];
#pragma unroll
        for (int j = 0; j < 8; j++) { acc[j][0] = 0u; acc[j][1] = 0u; }

        // ks-outer: 8 independent MMAs between dependent ones.
#pragma unroll
        for (int ks = 0; ks < 4; ks++) {
            uint2 b[8];
#pragma unroll
            for (int j = 0; j < 8; j++)
                b[j] = *(const uint2*)(Bc + (wn * 64 + j * 8 + g) * BSTRIDE +
                                       ((2 * r4) ^ px) + ks * 8);
#pragma unroll
            for (int j = 0; j < 8; j++)
                mma_f16(acc[j][0], acc[j][1], afr[ks], b[j].x, b[j].y);
        }

        // Stage tile t+2 into the buffer tile t-1 vacated last iteration.
        if (t + 2 < t1) {
            const int p2 = (p + 2) % 3;
            stage_tile(bbase + (uint32_t)p2 * BWORDS * 4u,
                       t2base + (uint32_t)p2 * 64u * 4u, t + 2, tid);
        }
        CP_COMMIT();     // unconditional: keeps wait_group numbering uniform

        // Epilogue IN PLACE: acc <- t2 - 2*acc (half2 scores).
#pragma unroll
        for (int j = 0; j < 8; j++) {
            __half2 t2p = *(const __half2*)&t2c[wn * 32 + j * 4 + r4];
            *(__half2*)&acc[j][0] = __hfma2(*(__half2*)&acc[j][0], neg2, t2p);
            *(__half2*)&acc[j][1] = __hfma2(*(__half2*)&acc[j][1], neg2, t2p);
        }

        // Per-slot tile minima + thresholds (own-tile min folded in: safe).
        float mf[2], thr[2];
#pragma unroll
        for (int s = 0; s < 2; s++) {
            __half2 m = *(__half2*)&acc[0][s];
#pragma unroll
            for (int j = 1; j < 8; j++) m = __hmin2(m, *(__half2*)&acc[j][s]);
            mf[s] = __half2float(__hmin(__low2half(m), __high2half(m)));
        }
        thr[0] = fminf(dec_f32(cmin[qloc0]), mf[0]) + EPS;
        thr[1] = fminf(dec_f32(cmin[qloc1]), mf[1]) + EPS;

        if (mf[0] <= thr[0] || mf[1] <= thr[1]) {
            const int n0 = t * NT + wn * 64 + 2 * r4;
#pragma unroll
            for (int s = 0; s < 2; s++) {
                if (mf[s] > thr[s]) continue;
                const int q = qbase + (s ? qloc1 : qloc0);
#pragma unroll
                for (int j = 0; j < 8; j++) {
                    __half2 sp = *(__half2*)&acc[j][s];
                    float slo = __half2float(__low2half(sp));
                    float shi = __half2float(__high2half(sp));
                    if (slo <= thr[s]) {
                        int pos = atomicAdd(&g_ccnt[q], 1);
                        if (pos < CAP) g_cand[q * CAP + pos] = n0 + j * 8;
                    }
                    if (shi <= thr[s]) {
                        int pos = atomicAdd(&g_ccnt[q], 1);
                        if (pos < CAP) g_cand[q * CAP + pos] = n0 + j * 8 + 1;
                    }
                }
            }
        }

        // Unconditional publish of tile minima to shared running min.
        float tm0 = mf[0], tm1 = mf[1];
        tm0 = fminf(tm0, __shfl_xor_sync(0xffffffffu, tm0, 1));
        tm0 = fminf(tm0, __shfl_xor_sync(0xffffffffu, tm0, 2));
        tm1 = fminf(tm1, __shfl_xor_sync(0xffffffffu, tm1, 1));
        tm1 = fminf(tm1, __shfl_xor_sync(0xffffffffu, tm1, 2));
        if (r4 == 0) {
            atomicMin(&cmin[qloc0], enc_f32(tm0));
            atomicMin(&cmin[qloc1], enc_f32(tm1));
        }

        CP_WAIT1();      // tile t+1 resident (t+2 may be in flight)
        __syncthreads();
    }
}

// ---- exact fp32 rescore (one warp per query) ------------------------------

__global__ void __launch_bounds__(256)
k_rescore(const float* __restrict__ codes, const float* __restrict__ train,
          int B) {
    const int lane = threadIdx.x & 31;
    const int q = blockIdx.x * 8 + (threadIdx.x >> 5);
    if (q >= B) return;

    float4 qv[16];
#pragma unroll
    for (int i = 0; i < 16; i++)
        qv[i] = __ldg(&((const float4*)codes)[(size_t)q * 16 + i]);

    unsigned long long best = 0xFFFFFFFFFFFFFFFFULL;
    int cnt = min(g_ccnt[q], CAP);
    for (int i = lane; i < cnt; i += 32) {
        int n = g_cand[q * CAP + i];
        const float4* tr = (const float4*)(train + (size_t)n * D);
        float dot = 0.f;
#pragma unroll
        for (int k = 0; k < 16; k++) {
            float4 tv = __ldg(&tr[k]);
            dot = fmaf(qv[k].x, tv.x, dot);
            dot = fmaf(qv[k].y, tv.y, dot);
            dot = fmaf(qv[k].z, tv.z, dot);
            dot = fmaf(qv[k].w, tv.w, dot);
        }
        float s = fmaf(-2.f, dot, g_t2[n]);
        unsigned long long key =
            ((unsigned long long)enc_f32(s) << 32) | (unsigned)n;
        best = min(best, key);
    }
#pragma unroll
    for (int off = 16; off >= 1; off >>= 1)
        best = min(best, __shfl_xor_sync(0xffffffffu, best, off));
    if (lane == 0) g_best[q] = best;
}

// ---- fused MLP: 4 queries per CTA, stage-2 chain splitting ----------------

__global__ void __launch_bounds__(256)
k_mlp(const float* __restrict__ train,
      const float* __restrict__ W1, const float* __restrict__ b1,
      const float* __restrict__ Wu, const float* __restrict__ bu,
      const float* __restrict__ Ws, const float* __restrict__ bs,
      float* __restrict__ out, int B, int N) {
    __shared__ float x_s[QB][D];
    __shared__ float h_s[QB][H];
    const int qb  = blockIdx.x * QB;
    const int tid = threadIdx.x;

    if (tid < QB * (D / 4)) {
        int q  = tid >> 4;
        int c4 = tid & 15;
        unsigned ch = (unsigned)(g_best[qb + q] & 0xFFFFFFFFULL);
        ch = min(ch, (unsigned)(N - 1));    // crash guard; logic keeps it < N
        ((float4*)&x_s[q][0])[c4] =
            __ldg(&((const float4*)train)[(size_t)ch * (D / 4) + c4]);
    }
    __syncthreads();

    {   // h = relu(x @ W1 + b1): thread owns columns tid, tid+256
        float a0[QB], a1[QB];
#pragma unroll
        for (int q = 0; q < QB; q++) { a0[q] = 0.f; a1[q] = 0.f; }
        const int c0 = tid, c1 = tid + 256;
#pragma unroll 4
        for (int d = 0; d < D; d++) {
            float w0 = __ldg(&W1[d * H + c0]);
            float w1 = __ldg(&W1[d * H + c1]);
#pragma unroll
            for (int q = 0; q < QB; q++) {
                float x = x_s[q][d];
                a0[q] = fmaf(x, w0, a0[q]);
                a1[q] = fmaf(x, w1, a1[q]);
            }
        }
        float bb0 = __ldg(&b1[c0]), bb1 = __ldg(&b1[c1]);
#pragma unroll
        for (int q = 0; q < QB; q++) {
            h_s[q][c0] = fmaxf(a0[q] + bb0, 0.f);
            h_s[q][c1] = fmaxf(a1[q] + bb1, 0.f);
        }
    }
    __syncthreads();

    {   // mu / logstd: thread -> (d, which, 2-query half); 4-way chain split
        const int d     = tid & 63;
        const int which = (tid >> 6) & 1;
        const int qh    = tid >> 7;
        const float* W  = which ? Ws : Wu;
        const float* bb = which ? bs : bu;
        float a0[4] = {0.f, 0.f, 0.f, 0.f};
        float a1[4] = {0.f, 0.f, 0.f, 0.f};
        const float* h0 = h_s[qh * 2];
        const float* h1 = h_s[qh * 2 + 1];
#pragma unroll 2
        for (int h = 0; h < H; h += 4) {
#pragma unroll
            for (int u = 0; u < 4; u++) {
                float w = __ldg(&W[(size_t)(h + u) * D + d]);
                a0[u] = fmaf(h0[h + u], w, a0[u]);
                a1[u] = fmaf(h1[h + u], w, a1[u]);
            }
        }
        float bvv = __ldg(&bb[d]);
        float r0 = (a0[0] + a0[1]) + (a0[2] + a0[3]) + bvv;
        float r1 = (a1[0] + a1[1]) + (a1[2] + a1[3]) + bvv;
        out[(size_t)which * B * D + (size_t)(qb + qh * 2) * D + d]     = r0;
        out[(size_t)which * B * D + (size_t)(qb + qh * 2 + 1) * D + d] = r1;
    }
}

// ---- launch ---------------------------------------------------------------

extern "C" void kernel_launch(void* const* d_in, const int* in_sizes, int n_in,
                              void* d_out, int out_size) {
    const float* codes = (const float*)d_in[0];
    const float* train = (const float*)d_in[1];
    const float* W1    = (const float*)d_in[2];
    const float* b1    = (const float*)d_in[3];
    const float* Wu    = (const float*)d_in[4];
    const float* bu    = (const float*)d_in[5];
    const float* Ws    = (const float*)d_in[6];
    const float* bs    = (const float*)d_in[7];
    float* out = (float*)d_out;

    const int B = in_sizes[0] / D;   // 2048
    const int N = in_sizes[1] / D;   // 100000

    // 3 prep chunks (keeps k_score at the ncu capture slot).
    const int CH = 33536;            // 131 * 256
    k_prep<<<131, 256>>>(train, N, B, 0, CH);
    k_prep<<<131, 256>>>(train, N, B, CH, CH);
    k_prep<<<131, 256>>>(train, N, B, 2 * CH, NPAD - 2 * CH);

    const int tiles_total = (N + NT - 1) / NT;          // 782
    const int qtiles      = B / QT;                     // 16
    const int nsplits     = 18;                         // 288 CTAs = 2/SM wave
    const int tps         = (tiles_total + nsplits - 1) / nsplits;

    const size_t smem = (size_t)SM_WORDS * sizeof(uint32_t);   // 62720 B
    cudaFuncSetAttribute(k_score, cudaFuncAttributeMaxDynamicSharedMemorySize,
                         (int)smem);
    k_score<<<dim3(qtiles, nsplits), 512, smem>>>(codes, tiles_total, tps);

    k_rescore<<<(B + 7) / 8, 256>>>(codes, train, B);
    k_mlp<<<B / QB, 256>>>(train, W1, b1, Wu, bu, Ws, bs, out, B, N);
}